// round 16
// baseline (speedup 1.0000x reference)
#include <cuda_runtime.h>
#include <cuda_bf16.h>
#include <math.h>

// ---------------- problem constants ----------------
#define BB 16
#define T0 512
#define TR 511
#define PP 1024
#define DD 2048
#define G4 8192   // 4*D
#define NL 4
#define NBLK 128

// ---------------- scratch (device globals; no allocation allowed) ----------------
__device__ __align__(16) float g_xg[(size_t)BB * T0 * G4];      // 256 MB
__device__ __align__(16) float g_bufA[(size_t)BB * T0 * PP];    // 32 MB
__device__ __align__(16) float g_hs[(size_t)BB * T0 * PP];      // 32 MB
__device__ __align__(16) uint4 g_whp[(size_t)1024 * 64 * 32];   // 32 MB packed Wh fragments
__device__ __align__(16) uint4 g_projp[(size_t)128 * 128 * 32]; // 8 MB packed proj fragments
__device__ __align__(16) __nv_bfloat16 g_wth[(size_t)8192 * 1024]; // 16 MB B^T hi [N][K]
__device__ __align__(16) __nv_bfloat16 g_wtl[(size_t)8192 * 1024]; // 16 MB B^T lo
__device__ __align__(16) __nv_bfloat16 g_axh[(size_t)BB * T0 * PP]; // A hi (GEMM input)
__device__ __align__(16) __nv_bfloat16 g_axl[(size_t)BB * T0 * PP]; // A lo
__device__ __align__(16) __nv_bfloat16 g_cah[(size_t)BB * T0 * DD]; // conv A hi
__device__ __align__(16) __nv_bfloat16 g_cal[(size_t)BB * T0 * DD]; // conv A lo
__device__ __align__(16) uint4 g_hfh[2048];                     // h A-fragments hi
__device__ __align__(16) uint4 g_hfl[2048];                     // h A-fragments lo
__device__ __align__(16) uint4 g_sfh[4096];                     // s A-fragments hi
__device__ __align__(16) uint4 g_sfl[4096];                     // s A-fragments lo
__device__ __align__(16) float g_c[BB * DD];
__device__ __align__(16) float g_h[BB * PP];
// 8 distributed barrier counters, each on its own 128-byte line
__device__ __align__(128) unsigned int g_bar8[8 * 32];

// ================= bf16 split helpers =================
__device__ __forceinline__ void bsplit2(float a, float b, unsigned& hi, unsigned& lo) {
    __nv_bfloat162 h2 = __floats2bfloat162_rn(a, b);
    float ra = a - __bfloat162float(h2.x);
    float rb = b - __bfloat162float(h2.y);
    __nv_bfloat162 l2 = __floats2bfloat162_rn(ra, rb);
    hi = *reinterpret_cast<unsigned*>(&h2);
    lo = *reinterpret_cast<unsigned*>(&l2);
}

__device__ __forceinline__ void mma_bf16(float* c, const unsigned* a, const unsigned* b) {
    asm volatile(
        "mma.sync.aligned.m16n8k16.row.col.f32.bf16.bf16.f32 "
        "{%0,%1,%2,%3},{%4,%5,%6,%7},{%8,%9},{%0,%1,%2,%3};"
        : "+f"(c[0]), "+f"(c[1]), "+f"(c[2]), "+f"(c[3])
        : "r"(a[0]), "r"(a[1]), "r"(a[2]), "r"(a[3]), "r"(b[0]), "r"(b[1]));
}

__device__ __forceinline__ void mma3(float* acc, const uint4& ah, const uint4& al, const uint4& bf) {
    unsigned bh[2] = {bf.x, bf.y};
    unsigned bl[2] = {bf.z, bf.w};
    mma_bf16(acc, &ah.x, bh);
    mma_bf16(acc, &ah.x, bl);
    mma_bf16(acc, &al.x, bh);
}

// ================= setup: init c/h + pack initial h fragments =================
__global__ __launch_bounds__(256) void setup_all(const float* __restrict__ state)
{
    unsigned* hfh32 = (unsigned*)g_hfh;
    unsigned* hfl32 = (unsigned*)g_hfl;
    int i = blockIdx.x * 256 + threadIdx.x;
    if (i < BB * DD) g_c[i] = state[i];
    if (i < BB * PP) {
        int b = i >> 10, p = i & 1023;
        g_h[i] = state[BB * DD + b * DD + p];
    }
    if (i < BB * 512) {
        int b = i >> 9;
        int j = i & 511;
        float v0 = state[BB * DD + b * DD + 2 * j];
        float v1 = state[BB * DD + b * DD + 2 * j + 1];
        int ks = j >> 3;
        int khalf = (j >> 2) & 1;
        int tq = j & 3;
        int lane = (b & 7) * 4 + tq;
        int comp = (b >> 3) + 2 * khalf;
        unsigned hiw, low;
        bsplit2(v0, v1, hiw, low);
        hfh32[((ks * 32 + lane) << 2) + comp] = hiw;
        hfl32[((ks * 32 + lane) << 2) + comp] = low;
    }
}

// ================= mma.sync fragment packer (Wh / proj) =================
__global__ __launch_bounds__(256) void pack_frag(
    const float* __restrict__ W, uint4* __restrict__ out, int N, int ksteps)
{
    __shared__ float tile[8][16][8];
    const int wlocal = threadIdx.x >> 5;
    const int lane = threadIdx.x & 31;
    const int wglob = blockIdx.x * 8 + wlocal;
    const int nt = wglob / ksteps;
    const int ks = wglob - nt * ksteps;

    {
        const int r = lane >> 1;
        const int cb = (lane & 1) * 4;
        float4 v = *(const float4*)&W[(size_t)(ks * 16 + r) * N + nt * 8 + cb];
        tile[wlocal][r][cb + 0] = v.x;
        tile[wlocal][r][cb + 1] = v.y;
        tile[wlocal][r][cb + 2] = v.z;
        tile[wlocal][r][cb + 3] = v.w;
    }
    __syncwarp();

    const int g = lane >> 2;
    const int t = lane & 3;
    float v00 = tile[wlocal][2 * t][g];
    float v01 = tile[wlocal][2 * t + 1][g];
    float v10 = tile[wlocal][2 * t + 8][g];
    float v11 = tile[wlocal][2 * t + 9][g];
    uint4 o;
    bsplit2(v00, v01, o.x, o.z);
    bsplit2(v10, v11, o.y, o.w);
    out[((size_t)(nt * ksteps + ks)) * 32 + lane] = o;
}

// ================= W^T transpose-pack: W[K,N] -> th/tl[N,K] bf16 =================
__global__ __launch_bounds__(256) void pack_wt(
    const float* __restrict__ W, __nv_bfloat16* __restrict__ th,
    __nv_bfloat16* __restrict__ tl, int K, int N)
{
    __shared__ float tsm[32][33];
    const int tx = threadIdx.x & 31;
    const int ty = threadIdx.x >> 5;
    const int n0 = blockIdx.x * 32;
    const int k0 = blockIdx.y * 32;
#pragma unroll
    for (int r = 0; r < 4; r++) {
        int k = k0 + ty + r * 8;
        tsm[ty + r * 8][tx] = W[(size_t)k * N + n0 + tx];
    }
    __syncthreads();
#pragma unroll
    for (int r = 0; r < 4; r++) {
        int n = n0 + ty + r * 8;
        int k = k0 + tx;
        float v = tsm[tx][ty + r * 8];
        __nv_bfloat16 hb = __float2bfloat16(v);
        __nv_bfloat16 lb = __float2bfloat16(v - __bfloat162float(hb));
        th[(size_t)n * K + k] = hb;
        tl[(size_t)n * K + k] = lb;
    }
}

// ================= elementwise fp32 -> bf16 hi/lo split =================
__global__ __launch_bounds__(256) void split_x(
    const float* __restrict__ x, __nv_bfloat16* __restrict__ xh,
    __nv_bfloat16* __restrict__ xl, size_t n4)
{
    size_t i = (size_t)blockIdx.x * 256 + threadIdx.x;
    if (i >= n4) return;
    float4 v = ((const float4*)x)[i];
    unsigned h0, l0, h1, l1;
    bsplit2(v.x, v.y, h0, l0);
    bsplit2(v.z, v.w, h1, l1);
    ((uint2*)xh)[i] = make_uint2(h0, h1);
    ((uint2*)xl)[i] = make_uint2(l0, l1);
}

// ================= conv im2col gather (pre-split bf16) =================
__global__ __launch_bounds__(256) void build_convA_sp(
    const __nv_bfloat16* __restrict__ lnh, const __nv_bfloat16* __restrict__ lnl,
    __nv_bfloat16* __restrict__ cah, __nv_bfloat16* __restrict__ cal)
{
    size_t idx = (size_t)blockIdx.x * 256 + threadIdx.x;
    if (idx >= (size_t)BB * TR * DD) return;
    int m = (int)(idx >> 11);
    int k = (int)(idx & 2047);
    int b = m / TR;
    int t = m - b * TR;
    int w = k >> 10;
    int p = k & 1023;
    size_t src = ((size_t)(b * T0 + t + w)) * PP + p;
    cah[idx] = lnh[src];
    cal[idx] = lnl[src];
}

// ================= pre-split bf16 GEMM (R14-proven, unchanged) =================
#define KPAD 40

__global__ __launch_bounds__(256, 2) void gemm_sp(
    const __nv_bfloat16* __restrict__ Ah, const __nv_bfloat16* __restrict__ Al,
    const __nv_bfloat16* __restrict__ Bh, const __nv_bfloat16* __restrict__ Bl,
    const float* __restrict__ bias, float* __restrict__ C,
    int M, int N, int K)
{
    if (blockIdx.x == 0 && blockIdx.y == 0 && threadIdx.x < 8)
        g_bar8[threadIdx.x * 32] = 0u;

    __shared__ __nv_bfloat16 sAh[128 * KPAD];
    __shared__ __nv_bfloat16 sAl[128 * KPAD];
    __shared__ __nv_bfloat16 sBh[128 * KPAD];
    __shared__ __nv_bfloat16 sBl[128 * KPAD];

    const int bm = blockIdx.y * 128;
    const int bn = blockIdx.x * 128;
    const int tid = threadIdx.x;
    const int lane = tid & 31;
    const int wid = tid >> 5;
    const int wm = (wid >> 2) * 64;
    const int wn = (wid & 3) * 32;
    const int lg = lane >> 2;
    const int lk = lane & 3;
    const int NT = K >> 5;

    const int srow0 = tid >> 2;
    const int sq = (tid & 3) * 8;

    float acc[4][4][4];
#pragma unroll
    for (int mt = 0; mt < 4; mt++)
#pragma unroll
        for (int nt = 0; nt < 4; nt++)
#pragma unroll
            for (int r = 0; r < 4; r++) acc[mt][nt][r] = 0.0f;

    for (int kt = 0; kt < NT; kt++) {
        const int kb0 = kt * 32;
#pragma unroll
        for (int i = 0; i < 2; i++) {
            const int row = srow0 + i * 64;
            uint4 va = make_uint4(0u, 0u, 0u, 0u), vb = va;
            if (bm + row < M) {
                va = *(const uint4*)&Ah[(size_t)(bm + row) * K + kb0 + sq];
                vb = *(const uint4*)&Al[(size_t)(bm + row) * K + kb0 + sq];
            }
            *(uint4*)&sAh[row * KPAD + sq] = va;
            *(uint4*)&sAl[row * KPAD + sq] = vb;
            uint4 wh = *(const uint4*)&Bh[(size_t)(bn + row) * K + kb0 + sq];
            uint4 wl = *(const uint4*)&Bl[(size_t)(bn + row) * K + kb0 + sq];
            *(uint4*)&sBh[row * KPAD + sq] = wh;
            *(uint4*)&sBl[row * KPAD + sq] = wl;
        }
        __syncthreads();

#pragma unroll
        for (int c = 0; c < 2; c++) {
            const int kb = c * 16 + 2 * lk;
            unsigned ah[4][4], al[4][4];
#pragma unroll
            for (int mt = 0; mt < 4; mt++) {
                const int row = wm + mt * 16 + lg;
                ah[mt][0] = *(const unsigned*)&sAh[row * KPAD + kb];
                ah[mt][1] = *(const unsigned*)&sAh[(row + 8) * KPAD + kb];
                ah[mt][2] = *(const unsigned*)&sAh[row * KPAD + kb + 8];
                ah[mt][3] = *(const unsigned*)&sAh[(row + 8) * KPAD + kb + 8];
                al[mt][0] = *(const unsigned*)&sAl[row * KPAD + kb];
                al[mt][1] = *(const unsigned*)&sAl[(row + 8) * KPAD + kb];
                al[mt][2] = *(const unsigned*)&sAl[row * KPAD + kb + 8];
                al[mt][3] = *(const unsigned*)&sAl[(row + 8) * KPAD + kb + 8];
            }
            unsigned bh[4][2], bl[4][2];
#pragma unroll
            for (int nt = 0; nt < 4; nt++) {
                const int col = wn + nt * 8 + lg;
                bh[nt][0] = *(const unsigned*)&sBh[col * KPAD + kb];
                bh[nt][1] = *(const unsigned*)&sBh[col * KPAD + kb + 8];
                bl[nt][0] = *(const unsigned*)&sBl[col * KPAD + kb];
                bl[nt][1] = *(const unsigned*)&sBl[col * KPAD + kb + 8];
            }
#pragma unroll
            for (int mt = 0; mt < 4; mt++)
#pragma unroll
                for (int nt = 0; nt < 4; nt++) {
                    mma_bf16(acc[mt][nt], ah[mt], bh[nt]);
                    mma_bf16(acc[mt][nt], ah[mt], bl[nt]);
                    mma_bf16(acc[mt][nt], al[mt], bh[nt]);
                }
        }
        __syncthreads();
    }

#pragma unroll
    for (int mt = 0; mt < 4; mt++)
#pragma unroll
        for (int nt = 0; nt < 4; nt++) {
            int row0 = bm + wm + mt * 16 + lg;
            int col0 = bn + wn + nt * 8 + lk * 2;
            float b0 = bias[col0], b1 = bias[col0 + 1];
            if (row0 < M) {
                float2 v = make_float2(acc[mt][nt][0] + b0, acc[mt][nt][1] + b1);
                *(float2*)&C[(size_t)row0 * N + col0] = v;
            }
            if (row0 + 8 < M) {
                float2 v = make_float2(acc[mt][nt][2] + b0, acc[mt][nt][3] + b1);
                *(float2*)&C[(size_t)(row0 + 8) * N + col0] = v;
            }
        }
}

// ================= persistent LSTM layer kernel: 1024 threads / 32 warps =================
__device__ __forceinline__ void grid_barrier(unsigned target16, int bid) {
    __syncthreads();
    if (threadIdx.x == 0) {
        asm volatile("red.release.gpu.global.add.u32 [%0], 1;"
                     :: "l"(&g_bar8[(bid & 7) * 32]) : "memory");
    }
    if (threadIdx.x < 8) {
        unsigned v;
        do {
            asm volatile("ld.acquire.gpu.global.u32 %0, [%1];"
                         : "=r"(v) : "l"(&g_bar8[threadIdx.x * 32]) : "memory");
        } while (v < target16);
    }
    __syncthreads();
}

// smem: h-frag hi 32KB + lo 32KB + red 16KB + gbuf 4KB = 84KB
#define SMEM_BYTES (84 * 1024)

__global__ __launch_bounds__(1024, 1) void lstm_persist(
    const float* __restrict__ xg,
    const uint4* __restrict__ whp,
    const uint4* __restrict__ projp,
    float* __restrict__ c,
    float* __restrict__ h,
    float* __restrict__ hs,
    int T)
{
    extern __shared__ __align__(16) char dynsmem[];
    uint4* sh_hi = (uint4*)dynsmem;                  // 2048 uint4
    uint4* sh_lo = sh_hi + 2048;                     // 2048 uint4
    float* red   = (float*)(dynsmem + 64 * 1024);    // 4096 floats
    float* gbuf  = red + 4096;                       // 1024 floats

    unsigned* sfh32 = (unsigned*)g_sfh;
    unsigned* sfl32 = (unsigned*)g_sfl;
    unsigned* hfh32 = (unsigned*)g_hfh;
    unsigned* hfl32 = (unsigned*)g_hfl;

    const int tid  = threadIdx.x;
    const int lane = tid & 31;
    const int warp = tid >> 5;        // 0..31
    const int bid  = blockIdx.x;
    const int d0   = bid * 16;
    const int p0   = bid * 8;

    // phase A mapping: 32 warps = 8 ntiles x 4 k-quarters (16 ksteps each)
    const int ntA = warp >> 2;        // 0..7
    const int kqA = warp & 3;         // 0..3
    const int gateA = ntA >> 1;
    const int halfA = ntA & 1;
    const int ntg  = gateA * 256 + bid * 2 + halfA;
    const uint4* wpA = whp + ((size_t)(ntg * 64 + kqA * 16)) * 32 + lane;

    const int lg = lane >> 2;
    const int lt = lane & 3;

    // cell-update mapping (tid < 128, identical to R10)
    const int cb = tid >> 3;
    const int cj = tid & 7;
    const int s_idx = (((bid * 32) + (cb & 7) * 4 + (cj & 3)) << 2) + ((cb >> 3) + 2 * ((cj >> 2) & 1));
    const int hb = tid >> 3;
    const int hp = tid & 7;
    const int h_idx = ((((bid >> 1) * 32) + (hb & 7) * 4 + (hp >> 1)) << 2) + ((hb >> 3) + 2 * (bid & 1));

    unsigned epoch = 0;

    for (int t = 0; t < T; t++) {
        // ---- prefetch xg + old c (tid < 128) ----
        float2 xgv[4], cold;
        if (tid < 128) {
            const size_t xrow = ((size_t)(cb * T + t)) * G4;
            const int dloc = d0 + 2 * cj;
#pragma unroll
            for (int g = 0; g < 4; g++)
                xgv[g] = *(const float2*)&xg[xrow + g * DD + dloc];
            cold = *(const float2*)&c[cb * DD + dloc];
        }

        // ---- stage h A-fragments global -> smem (1024 threads, 2 iters) ----
#pragma unroll
        for (int i = 0; i < 2; i++) {
            const int idx = tid + i * 1024;
            sh_hi[idx] = __ldcg(&g_hfh[idx]);
            sh_lo[idx] = __ldcg(&g_hfl[idx]);
        }
        __syncthreads();

        // ---- phase A mma: 16 ksteps per warp, 2 accums ----
        {
            float a0[4] = {0.f, 0.f, 0.f, 0.f};
            float a1[4] = {0.f, 0.f, 0.f, 0.f};
            const uint4* aph = sh_hi + (kqA * 16) * 32 + lane;
            const uint4* apl = sh_lo + (kqA * 16) * 32 + lane;
#pragma unroll
            for (int ks = 0; ks < 16; ks += 2) {
                uint4 b0 = wpA[(size_t)(ks + 0) * 32];
                uint4 b1 = wpA[(size_t)(ks + 1) * 32];
                uint4 ah0 = aph[(ks + 0) * 32], al0 = apl[(ks + 0) * 32];
                uint4 ah1 = aph[(ks + 1) * 32], al1 = apl[(ks + 1) * 32];
                mma3(a0, ah0, al0, b0);
                mma3(a1, ah1, al1, b1);
            }
            float acc[4];
#pragma unroll
            for (int r = 0; r < 4; r++) acc[r] = a0[r] + a1[r];

            // 4-way k-quarter reduce
            if (kqA != 0) {
#pragma unroll
                for (int r = 0; r < 4; r++) red[warp * 128 + lane * 4 + r] = acc[r];
            }
            __syncthreads();
            if (kqA == 0) {
#pragma unroll
                for (int r = 0; r < 4; r++)
                    acc[r] += red[(warp + 1) * 128 + lane * 4 + r]
                            + red[(warp + 2) * 128 + lane * 4 + r]
                            + red[(warp + 3) * 128 + lane * 4 + r];
                const int ddb = halfA * 8 + 2 * lt;
                gbuf[(lg * 16 + ddb) * 4 + gateA]           = acc[0];
                gbuf[(lg * 16 + ddb + 1) * 4 + gateA]       = acc[1];
                gbuf[((lg + 8) * 16 + ddb) * 4 + gateA]     = acc[2];
                gbuf[((lg + 8) * 16 + ddb + 1) * 4 + gateA] = acc[3];
            }
        }
        __syncthreads();

        // ---- cell update (tid < 128, identical to R10) ----
        if (tid < 128) {
            float4 gv0 = *(float4*)&gbuf[(cb * 16 + 2 * cj) * 4];
            float4 gv1 = *(float4*)&gbuf[(cb * 16 + 2 * cj + 1) * 4];
            float si0 = 1.0f / (1.0f + expf(-(gv0.x + xgv[0].x)));
            float sj0 = tanhf(gv0.y + xgv[1].x);
            float sf0 = 1.0f / (1.0f + expf(-(gv0.z + xgv[2].x + 1.0f)));
            float so0 = 1.0f / (1.0f + expf(-(gv0.w + xgv[3].x)));
            float cn0 = sf0 * cold.x + si0 * sj0;
            float s0 = so0 * tanhf(cn0);
            float si1 = 1.0f / (1.0f + expf(-(gv1.x + xgv[0].y)));
            float sj1 = tanhf(gv1.y + xgv[1].y);
            float sf1 = 1.0f / (1.0f + expf(-(gv1.z + xgv[2].y + 1.0f)));
            float so1 = 1.0f / (1.0f + expf(-(gv1.w + xgv[3].y)));
            float cn1 = sf1 * cold.y + si1 * sj1;
            float s1 = so1 * tanhf(cn1);

            *(float2*)&c[cb * DD + d0 + 2 * cj] = make_float2(cn0, cn1);

            unsigned hiw, low;
            bsplit2(s0, s1, hiw, low);
            sfh32[s_idx] = hiw;
            sfl32[s_idx] = low;
        }

        epoch++;
        grid_barrier(epoch * 16, bid);

        // ---- phase B mma: 32 warps x 4 ksteps, 2 accums ----
        {
            float q0[4] = {0.f, 0.f, 0.f, 0.f};
            float q1[4] = {0.f, 0.f, 0.f, 0.f};
            const uint4* pp  = projp + ((size_t)(bid * 128 + warp * 4)) * 32 + lane;
            const uint4* aph = g_sfh + (warp * 4) * 32 + lane;
            const uint4* apl = g_sfl + (warp * 4) * 32 + lane;
#pragma unroll
            for (int ks = 0; ks < 4; ks += 2) {
                uint4 b0 = pp[(size_t)(ks + 0) * 32];
                uint4 b1 = pp[(size_t)(ks + 1) * 32];
                uint4 ah0 = __ldcg(&aph[(ks + 0) * 32]);
                uint4 al0 = __ldcg(&apl[(ks + 0) * 32]);
                uint4 ah1 = __ldcg(&aph[(ks + 1) * 32]);
                uint4 al1 = __ldcg(&apl[(ks + 1) * 32]);
                mma3(q0, ah0, al0, b0);
                mma3(q1, ah1, al1, b1);
            }
#pragma unroll
            for (int r = 0; r < 4; r++) red[warp * 128 + lane * 4 + r] = q0[r] + q1[r];
        }
        __syncthreads();

        if (tid < 128) {
            const int b = hb;
            const int p = hp;
            const int rl = (b & 7) * 4 + (p >> 1);
            const int rr = (b < 8) ? (p & 1) : (2 + (p & 1));
            float v = 0.0f;
#pragma unroll
            for (int w = 0; w < 32; w++) v += red[w * 128 + rl * 4 + rr];
            h[b * PP + p0 + p] = v;
            hs[((size_t)(b * T + t)) * PP + p0 + p] = v;
            float vp = __shfl_xor_sync(0xffffffffu, v, 1);
            if ((tid & 1) == 0) {
                unsigned hiw, low;
                bsplit2(v, vp, hiw, low);
                hfh32[h_idx] = hiw;
                hfl32[h_idx] = low;
            }
        }

        epoch++;
        grid_barrier(epoch * 16, bid);
    }
}

// ================= LayerNorm over rows of 1024 (+ bf16 hi/lo split outputs) =================
__global__ __launch_bounds__(256) void ln_kernel(
    const float* __restrict__ x, const float* __restrict__ gam,
    const float* __restrict__ bet, float* __restrict__ y,
    __nv_bfloat16* __restrict__ yh, __nv_bfloat16* __restrict__ yl)
{
    __shared__ float sred[256];
    const size_t r = blockIdx.x;
    const float* xr = x + r * PP;
    const int tid = threadIdx.x;

    float v[4];
#pragma unroll
    for (int i = 0; i < 4; i++) v[i] = xr[tid + i * 256];
    float sm = v[0] + v[1] + v[2] + v[3];
    sred[tid] = sm;
    __syncthreads();
    for (int off = 128; off > 0; off >>= 1) {
        if (tid < off) sred[tid] += sred[tid + off];
        __syncthreads();
    }
    float mean = sred[0] * (1.0f / 1024.0f);
    __syncthreads();

    float q = 0.0f;
#pragma unroll
    for (int i = 0; i < 4; i++) { float d = v[i] - mean; q += d * d; }
    sred[tid] = q;
    __syncthreads();
    for (int off = 128; off > 0; off >>= 1) {
        if (tid < off) sred[tid] += sred[tid + off];
        __syncthreads();
    }
    float inv = rsqrtf(sred[0] * (1.0f / 1024.0f) + 1e-3f);

#pragma unroll
    for (int i = 0; i < 4; i++) {
        int col = tid + i * 256;
        float o = (v[i] - mean) * inv * gam[col] + bet[col];
        y[r * PP + col] = o;
        __nv_bfloat16 hb = __float2bfloat16(o);
        yh[r * PP + col] = hb;
        yl[r * PP + col] = __float2bfloat16(o - __bfloat162float(hb));
    }
}

// ================= tail =================
__global__ __launch_bounds__(256) void write_tail(
    const float* __restrict__ c, const float* __restrict__ h, float* __restrict__ out)
{
    const size_t base = (size_t)BB * TR * PP;
    int i = blockIdx.x * 256 + threadIdx.x;
    if (i < BB * DD) out[base + i] = c[i];
    if (i < BB * PP) out[base + BB * DD + i] = h[i];
}

// ================= orchestration =================
extern "C" void kernel_launch(void* const* d_in, const int* in_sizes, int n_in,
                              void* d_out, int out_size)
{
    const float* inputs  = (const float*)d_in[0];
    const float* state   = (const float*)d_in[1];
    const float* kernels = (const float*)d_in[2];
    const float* biases  = (const float*)d_in[3];
    const float* projs   = (const float*)d_in[4];
    const float* gamma   = (const float*)d_in[5];
    const float* beta    = (const float*)d_in[6];
    const float* convw   = (const float*)d_in[7];
    const float* convb   = (const float*)d_in[8];
    float* out = (float*)d_out;

    float *xg, *bufA, *hs, *c, *h;
    uint4 *whp, *projp;
    __nv_bfloat16 *wth, *wtl, *axh, *axl, *cah, *cal;
    cudaGetSymbolAddress((void**)&xg,    g_xg);
    cudaGetSymbolAddress((void**)&bufA,  g_bufA);
    cudaGetSymbolAddress((void**)&hs,    g_hs);
    cudaGetSymbolAddress((void**)&whp,   g_whp);
    cudaGetSymbolAddress((void**)&projp, g_projp);
    cudaGetSymbolAddress((void**)&wth,   g_wth);
    cudaGetSymbolAddress((void**)&wtl,   g_wtl);
    cudaGetSymbolAddress((void**)&axh,   g_axh);
    cudaGetSymbolAddress((void**)&axl,   g_axl);
    cudaGetSymbolAddress((void**)&cah,   g_cah);
    cudaGetSymbolAddress((void**)&cal,   g_cal);
    cudaGetSymbolAddress((void**)&c,     g_c);
    cudaGetSymbolAddress((void**)&h,     g_h);

    static int smem_set = 0;
    if (!smem_set) {
        cudaFuncSetAttribute(lstm_persist, cudaFuncAttributeMaxDynamicSharedMemorySize, SMEM_BYTES);
        smem_set = 1;
    }

    setup_all<<<128, 256>>>(state);

    split_x<<<(int)(((size_t)BB * T0 * PP / 4 + 255) / 256), 256>>>(
        inputs, axh, axl, (size_t)BB * T0 * PP / 4);

    int T = T0;
    for (int l = 0; l < NL; l++) {
        const float* Wx = kernels + (size_t)l * 2 * PP * G4;
        const float* Wh = Wx + (size_t)PP * G4;
        const float* bi = biases + (size_t)l * G4;
        const float* pr = projs + (size_t)l * DD * PP;
        const int M = BB * T;

        pack_frag<<<(1024 * 64) / 8, 256>>>(Wh, whp, G4, 64);
        pack_frag<<<(128 * 128) / 8, 256>>>(pr, projp, PP, 128);

        pack_wt<<<dim3(G4 / 32, PP / 32), 256>>>(Wx, wth, wtl, PP, G4);

        dim3 g1(G4 / 128, (M + 127) / 128);
        gemm_sp<<<g1, 256>>>(axh, axl, wth, wtl, bi, xg, M, G4, PP);

        lstm_persist<<<NBLK, 1024, SMEM_BYTES>>>(xg, whp, projp, c, h, hs, T);

        float* lnout = (l == 3) ? out : bufA;
        ln_kernel<<<BB * T, 256>>>(hs, gamma, beta, lnout, axh, axl);

        if (l == 1) {
            build_convA_sp<<<(int)(((size_t)BB * TR * DD + 255) / 256), 256>>>(axh, axl, cah, cal);
            pack_wt<<<dim3(PP / 32, DD / 32), 256>>>(convw, wth, wtl, DD, PP);
            dim3 g2(PP / 128, (BB * TR + 127) / 128);
            gemm_sp<<<g2, 256>>>(cah, cal, wth, wtl, convb, bufA, BB * TR, PP, DD);
            split_x<<<(int)(((size_t)BB * TR * PP / 4 + 255) / 256), 256>>>(
                bufA, axh, axl, (size_t)BB * TR * PP / 4);
            T = TR;
        }
    }

    write_tail<<<128, 256>>>(c, h, out);
}

// round 17
// speedup vs baseline: 1.0209x; 1.0209x over previous
#include <cuda_runtime.h>
#include <cuda_bf16.h>
#include <math.h>

// ---------------- problem constants ----------------
#define BB 16
#define T0 512
#define TR 511
#define PP 1024
#define DD 2048
#define G4 8192   // 4*D
#define NL 4
#define NBLK 128

// ---------------- scratch (device globals; no allocation allowed) ----------------
__device__ __align__(16) float g_xg[(size_t)BB * T0 * G4];      // 256 MB
__device__ __align__(16) float g_bufA[(size_t)BB * T0 * PP];    // 32 MB
__device__ __align__(16) float g_hs[(size_t)BB * T0 * PP];      // 32 MB
__device__ __align__(16) uint4 g_whp[(size_t)1024 * 64 * 32];   // 32 MB packed Wh fragments
__device__ __align__(16) uint4 g_projp[(size_t)128 * 128 * 32]; // 8 MB packed proj fragments
__device__ __align__(16) __nv_bfloat16 g_wth[(size_t)8192 * 1024]; // 16 MB B^T hi [N][K]
__device__ __align__(16) __nv_bfloat16 g_wtl[(size_t)8192 * 1024]; // 16 MB B^T lo
__device__ __align__(16) __nv_bfloat16 g_axh[(size_t)BB * T0 * PP]; // A hi (GEMM input)
__device__ __align__(16) __nv_bfloat16 g_axl[(size_t)BB * T0 * PP]; // A lo
__device__ __align__(16) __nv_bfloat16 g_cah[(size_t)BB * T0 * DD]; // conv A hi
__device__ __align__(16) __nv_bfloat16 g_cal[(size_t)BB * T0 * DD]; // conv A lo
__device__ __align__(16) uint4 g_hfh[2048];                     // h A-fragments hi
__device__ __align__(16) uint4 g_hfl[2048];                     // h A-fragments lo
__device__ __align__(16) uint4 g_sfh[4096];                     // s A-fragments hi
__device__ __align__(16) uint4 g_sfl[4096];                     // s A-fragments lo
__device__ __align__(16) float g_c[BB * DD];
__device__ __align__(16) float g_h[BB * PP];
// 8 distributed barrier counters + 128 per-block s-ready flags (128B lines)
__device__ __align__(128) unsigned int g_bar8[8 * 32];
__device__ __align__(128) unsigned int g_sflag[128 * 32];

// ================= bf16 split helpers =================
__device__ __forceinline__ void bsplit2(float a, float b, unsigned& hi, unsigned& lo) {
    __nv_bfloat162 h2 = __floats2bfloat162_rn(a, b);
    float ra = a - __bfloat162float(h2.x);
    float rb = b - __bfloat162float(h2.y);
    __nv_bfloat162 l2 = __floats2bfloat162_rn(ra, rb);
    hi = *reinterpret_cast<unsigned*>(&h2);
    lo = *reinterpret_cast<unsigned*>(&l2);
}

__device__ __forceinline__ void mma_bf16(float* c, const unsigned* a, const unsigned* b) {
    asm volatile(
        "mma.sync.aligned.m16n8k16.row.col.f32.bf16.bf16.f32 "
        "{%0,%1,%2,%3},{%4,%5,%6,%7},{%8,%9},{%0,%1,%2,%3};"
        : "+f"(c[0]), "+f"(c[1]), "+f"(c[2]), "+f"(c[3])
        : "r"(a[0]), "r"(a[1]), "r"(a[2]), "r"(a[3]), "r"(b[0]), "r"(b[1]));
}

__device__ __forceinline__ void mma3(float* acc, const uint4& ah, const uint4& al, const uint4& bf) {
    unsigned bh[2] = {bf.x, bf.y};
    unsigned bl[2] = {bf.z, bf.w};
    mma_bf16(acc, &ah.x, bh);
    mma_bf16(acc, &ah.x, bl);
    mma_bf16(acc, &al.x, bh);
}

// ================= setup: init c/h + pack initial h fragments =================
__global__ __launch_bounds__(256) void setup_all(const float* __restrict__ state)
{
    unsigned* hfh32 = (unsigned*)g_hfh;
    unsigned* hfl32 = (unsigned*)g_hfl;
    int i = blockIdx.x * 256 + threadIdx.x;
    if (i < BB * DD) g_c[i] = state[i];
    if (i < BB * PP) {
        int b = i >> 10, p = i & 1023;
        g_h[i] = state[BB * DD + b * DD + p];
    }
    if (i < BB * 512) {
        int b = i >> 9;
        int j = i & 511;
        float v0 = state[BB * DD + b * DD + 2 * j];
        float v1 = state[BB * DD + b * DD + 2 * j + 1];
        int ks = j >> 3;
        int khalf = (j >> 2) & 1;
        int tq = j & 3;
        int lane = (b & 7) * 4 + tq;
        int comp = (b >> 3) + 2 * khalf;
        unsigned hiw, low;
        bsplit2(v0, v1, hiw, low);
        hfh32[((ks * 32 + lane) << 2) + comp] = hiw;
        hfl32[((ks * 32 + lane) << 2) + comp] = low;
    }
}

// ================= mma.sync fragment packer (Wh / proj) =================
__global__ __launch_bounds__(256) void pack_frag(
    const float* __restrict__ W, uint4* __restrict__ out, int N, int ksteps)
{
    __shared__ float tile[8][16][8];
    const int wlocal = threadIdx.x >> 5;
    const int lane = threadIdx.x & 31;
    const int wglob = blockIdx.x * 8 + wlocal;
    const int nt = wglob / ksteps;
    const int ks = wglob - nt * ksteps;

    {
        const int r = lane >> 1;
        const int cb = (lane & 1) * 4;
        float4 v = *(const float4*)&W[(size_t)(ks * 16 + r) * N + nt * 8 + cb];
        tile[wlocal][r][cb + 0] = v.x;
        tile[wlocal][r][cb + 1] = v.y;
        tile[wlocal][r][cb + 2] = v.z;
        tile[wlocal][r][cb + 3] = v.w;
    }
    __syncwarp();

    const int g = lane >> 2;
    const int t = lane & 3;
    float v00 = tile[wlocal][2 * t][g];
    float v01 = tile[wlocal][2 * t + 1][g];
    float v10 = tile[wlocal][2 * t + 8][g];
    float v11 = tile[wlocal][2 * t + 9][g];
    uint4 o;
    bsplit2(v00, v01, o.x, o.z);
    bsplit2(v10, v11, o.y, o.w);
    out[((size_t)(nt * ksteps + ks)) * 32 + lane] = o;
}

// ================= W^T transpose-pack: W[K,N] -> th/tl[N,K] bf16 =================
__global__ __launch_bounds__(256) void pack_wt(
    const float* __restrict__ W, __nv_bfloat16* __restrict__ th,
    __nv_bfloat16* __restrict__ tl, int K, int N)
{
    __shared__ float tsm[32][33];
    const int tx = threadIdx.x & 31;
    const int ty = threadIdx.x >> 5;
    const int n0 = blockIdx.x * 32;
    const int k0 = blockIdx.y * 32;
#pragma unroll
    for (int r = 0; r < 4; r++) {
        int k = k0 + ty + r * 8;
        tsm[ty + r * 8][tx] = W[(size_t)k * N + n0 + tx];
    }
    __syncthreads();
#pragma unroll
    for (int r = 0; r < 4; r++) {
        int n = n0 + ty + r * 8;
        int k = k0 + tx;
        float v = tsm[tx][ty + r * 8];
        __nv_bfloat16 hb = __float2bfloat16(v);
        __nv_bfloat16 lb = __float2bfloat16(v - __bfloat162float(hb));
        th[(size_t)n * K + k] = hb;
        tl[(size_t)n * K + k] = lb;
    }
}

// ================= elementwise fp32 -> bf16 hi/lo split =================
__global__ __launch_bounds__(256) void split_x(
    const float* __restrict__ x, __nv_bfloat16* __restrict__ xh,
    __nv_bfloat16* __restrict__ xl, size_t n4)
{
    size_t i = (size_t)blockIdx.x * 256 + threadIdx.x;
    if (i >= n4) return;
    float4 v = ((const float4*)x)[i];
    unsigned h0, l0, h1, l1;
    bsplit2(v.x, v.y, h0, l0);
    bsplit2(v.z, v.w, h1, l1);
    ((uint2*)xh)[i] = make_uint2(h0, h1);
    ((uint2*)xl)[i] = make_uint2(l0, l1);
}

// ================= conv im2col gather (pre-split bf16) =================
__global__ __launch_bounds__(256) void build_convA_sp(
    const __nv_bfloat16* __restrict__ lnh, const __nv_bfloat16* __restrict__ lnl,
    __nv_bfloat16* __restrict__ cah, __nv_bfloat16* __restrict__ cal)
{
    size_t idx = (size_t)blockIdx.x * 256 + threadIdx.x;
    if (idx >= (size_t)BB * TR * DD) return;
    int m = (int)(idx >> 11);
    int k = (int)(idx & 2047);
    int b = m / TR;
    int t = m - b * TR;
    int w = k >> 10;
    int p = k & 1023;
    size_t src = ((size_t)(b * T0 + t + w)) * PP + p;
    cah[idx] = lnh[src];
    cal[idx] = lnl[src];
}

// ================= pre-split bf16 GEMM (R14-proven) =================
#define KPAD 40

__global__ __launch_bounds__(256, 2) void gemm_sp(
    const __nv_bfloat16* __restrict__ Ah, const __nv_bfloat16* __restrict__ Al,
    const __nv_bfloat16* __restrict__ Bh, const __nv_bfloat16* __restrict__ Bl,
    const float* __restrict__ bias, float* __restrict__ C,
    int M, int N, int K)
{
    // reset barrier counters + per-block s-ready flags for the next lstm launch
    if (blockIdx.x == 0 && blockIdx.y == 0) {
        if (threadIdx.x < 8) g_bar8[threadIdx.x * 32] = 0u;
        if (threadIdx.x < 128) g_sflag[threadIdx.x * 32] = 0u;
    }

    __shared__ __nv_bfloat16 sAh[128 * KPAD];
    __shared__ __nv_bfloat16 sAl[128 * KPAD];
    __shared__ __nv_bfloat16 sBh[128 * KPAD];
    __shared__ __nv_bfloat16 sBl[128 * KPAD];

    const int bm = blockIdx.y * 128;
    const int bn = blockIdx.x * 128;
    const int tid = threadIdx.x;
    const int lane = tid & 31;
    const int wid = tid >> 5;
    const int wm = (wid >> 2) * 64;
    const int wn = (wid & 3) * 32;
    const int lg = lane >> 2;
    const int lk = lane & 3;
    const int NT = K >> 5;

    const int srow0 = tid >> 2;
    const int sq = (tid & 3) * 8;

    float acc[4][4][4];
#pragma unroll
    for (int mt = 0; mt < 4; mt++)
#pragma unroll
        for (int nt = 0; nt < 4; nt++)
#pragma unroll
            for (int r = 0; r < 4; r++) acc[mt][nt][r] = 0.0f;

    for (int kt = 0; kt < NT; kt++) {
        const int kb0 = kt * 32;
#pragma unroll
        for (int i = 0; i < 2; i++) {
            const int row = srow0 + i * 64;
            uint4 va = make_uint4(0u, 0u, 0u, 0u), vb = va;
            if (bm + row < M) {
                va = *(const uint4*)&Ah[(size_t)(bm + row) * K + kb0 + sq];
                vb = *(const uint4*)&Al[(size_t)(bm + row) * K + kb0 + sq];
            }
            *(uint4*)&sAh[row * KPAD + sq] = va;
            *(uint4*)&sAl[row * KPAD + sq] = vb;
            uint4 wh = *(const uint4*)&Bh[(size_t)(bn + row) * K + kb0 + sq];
            uint4 wl = *(const uint4*)&Bl[(size_t)(bn + row) * K + kb0 + sq];
            *(uint4*)&sBh[row * KPAD + sq] = wh;
            *(uint4*)&sBl[row * KPAD + sq] = wl;
        }
        __syncthreads();

#pragma unroll
        for (int c = 0; c < 2; c++) {
            const int kb = c * 16 + 2 * lk;
            unsigned ah[4][4], al[4][4];
#pragma unroll
            for (int mt = 0; mt < 4; mt++) {
                const int row = wm + mt * 16 + lg;
                ah[mt][0] = *(const unsigned*)&sAh[row * KPAD + kb];
                ah[mt][1] = *(const unsigned*)&sAh[(row + 8) * KPAD + kb];
                ah[mt][2] = *(const unsigned*)&sAh[row * KPAD + kb + 8];
                ah[mt][3] = *(const unsigned*)&sAh[(row + 8) * KPAD + kb + 8];
                al[mt][0] = *(const unsigned*)&sAl[row * KPAD + kb];
                al[mt][1] = *(const unsigned*)&sAl[(row + 8) * KPAD + kb];
                al[mt][2] = *(const unsigned*)&sAl[row * KPAD + kb + 8];
                al[mt][3] = *(const unsigned*)&sAl[(row + 8) * KPAD + kb + 8];
            }
            unsigned bh[4][2], bl[4][2];
#pragma unroll
            for (int nt = 0; nt < 4; nt++) {
                const int col = wn + nt * 8 + lg;
                bh[nt][0] = *(const unsigned*)&sBh[col * KPAD + kb];
                bh[nt][1] = *(const unsigned*)&sBh[col * KPAD + kb + 8];
                bl[nt][0] = *(const unsigned*)&sBl[col * KPAD + kb];
                bl[nt][1] = *(const unsigned*)&sBl[col * KPAD + kb + 8];
            }
#pragma unroll
            for (int mt = 0; mt < 4; mt++)
#pragma unroll
                for (int nt = 0; nt < 4; nt++) {
                    mma_bf16(acc[mt][nt], ah[mt], bh[nt]);
                    mma_bf16(acc[mt][nt], ah[mt], bl[nt]);
                    mma_bf16(acc[mt][nt], al[mt], bh[nt]);
                }
        }
        __syncthreads();
    }

#pragma unroll
    for (int mt = 0; mt < 4; mt++)
#pragma unroll
        for (int nt = 0; nt < 4; nt++) {
            int row0 = bm + wm + mt * 16 + lg;
            int col0 = bn + wn + nt * 8 + lk * 2;
            float b0 = bias[col0], b1 = bias[col0 + 1];
            if (row0 < M) {
                float2 v = make_float2(acc[mt][nt][0] + b0, acc[mt][nt][1] + b1);
                *(float2*)&C[(size_t)row0 * N + col0] = v;
            }
            if (row0 + 8 < M) {
                float2 v = make_float2(acc[mt][nt][2] + b0, acc[mt][nt][3] + b1);
                *(float2*)&C[(size_t)(row0 + 8) * N + col0] = v;
            }
        }
}

// ================= persistent LSTM layer kernel (512 thr, flag-synced phase B) =================
__device__ __forceinline__ void grid_barrier(unsigned target16, int bid) {
    __syncthreads();
    if (threadIdx.x == 0) {
        asm volatile("red.release.gpu.global.add.u32 [%0], 1;"
                     :: "l"(&g_bar8[(bid & 7) * 32]) : "memory");
    }
    if (threadIdx.x < 8) {
        unsigned v;
        do {
            asm volatile("ld.acquire.gpu.global.u32 %0, [%1];"
                         : "=r"(v) : "l"(&g_bar8[threadIdx.x * 32]) : "memory");
        } while (v < target16);
    }
    __syncthreads();
}

#define SMEM_BYTES (72 * 1024)

__global__ __launch_bounds__(512, 1) void lstm_persist(
    const float* __restrict__ xg,
    const uint4* __restrict__ whp,
    const uint4* __restrict__ projp,
    float* __restrict__ c,
    float* __restrict__ h,
    float* __restrict__ hs,
    int T)
{
    extern __shared__ __align__(16) char dynsmem[];
    uint4* sh_hi = (uint4*)dynsmem;
    uint4* sh_lo = sh_hi + 2048;
    float* red   = (float*)(dynsmem + 64 * 1024);
    float* gbuf  = red + 1024;

    unsigned* sfh32 = (unsigned*)g_sfh;
    unsigned* sfl32 = (unsigned*)g_sfl;
    unsigned* hfh32 = (unsigned*)g_hfh;
    unsigned* hfl32 = (unsigned*)g_hfl;

    const int tid  = threadIdx.x;
    const int lane = tid & 31;
    const int warp = tid >> 5;
    const int bid  = blockIdx.x;
    const int d0   = bid * 16;
    const int p0   = bid * 8;

    const int gateA = warp >> 1;
    const int halfA = warp & 1;
    const int ntA  = gateA * 256 + bid * 2 + halfA;
    const uint4* wpA = whp + ((size_t)(ntA * 64)) * 32 + lane;

    const int lg = lane >> 2;
    const int lt = lane & 3;

    const int cb = tid >> 3;
    const int cj = tid & 7;
    const int s_idx = (((bid * 32) + (cb & 7) * 4 + (cj & 3)) << 2) + ((cb >> 3) + 2 * ((cj >> 2) & 1));
    const int hb = tid >> 3;
    const int hp = tid & 7;
    const int h_idx = ((((bid >> 1) * 32) + (hb & 7) * 4 + (hp >> 1)) << 2) + ((hb >> 3) + 2 * (bid & 1));

    // phase B pointers (static across steps)
    const uint4* pp  = projp + ((size_t)(bid * 128 + warp * 8)) * 32 + lane;
    const uint4* aph = g_sfh + (warp * 8) * 32 + lane;
    const uint4* apl = g_sfl + (warp * 8) * 32 + lane;
    const unsigned* myflag = &g_sflag[((warp << 3) + lane) * 32];   // lane<8 only

    for (int t = 0; t < T; t++) {
        // ---- prefetch xg + old c ----
        float2 xgv[4], cold;
        if (tid < 128) {
            const size_t xrow = ((size_t)(cb * T + t)) * G4;
            const int dloc = d0 + 2 * cj;
#pragma unroll
            for (int g = 0; g < 4; g++)
                xgv[g] = *(const float2*)&xg[xrow + g * DD + dloc];
            cold = *(const float2*)&c[cb * DD + dloc];
        }

        // ---- stage h A-fragments global -> smem ----
#pragma unroll
        for (int i = 0; i < 4; i++) {
            const int idx = tid + i * 512;
            sh_hi[idx] = __ldcg(&g_hfh[idx]);
            sh_lo[idx] = __ldcg(&g_hfl[idx]);
        }
        __syncthreads();

        // ---- phase A mma (warps 0-7, full K, 4 accums) ----
        if (warp < 8) {
            float a0[4] = {0.f, 0.f, 0.f, 0.f};
            float a1[4] = {0.f, 0.f, 0.f, 0.f};
            float a2[4] = {0.f, 0.f, 0.f, 0.f};
            float a3[4] = {0.f, 0.f, 0.f, 0.f};
            const uint4* saph = sh_hi + lane;
            const uint4* sapl = sh_lo + lane;
#pragma unroll 2
            for (int ks = 0; ks < 64; ks += 4) {
                uint4 b0 = wpA[(size_t)(ks + 0) * 32];
                uint4 b1 = wpA[(size_t)(ks + 1) * 32];
                uint4 b2 = wpA[(size_t)(ks + 2) * 32];
                uint4 b3 = wpA[(size_t)(ks + 3) * 32];
                uint4 ah0 = saph[(ks + 0) * 32], al0 = sapl[(ks + 0) * 32];
                uint4 ah1 = saph[(ks + 1) * 32], al1 = sapl[(ks + 1) * 32];
                uint4 ah2 = saph[(ks + 2) * 32], al2 = sapl[(ks + 2) * 32];
                uint4 ah3 = saph[(ks + 3) * 32], al3 = sapl[(ks + 3) * 32];
                mma3(a0, ah0, al0, b0);
                mma3(a1, ah1, al1, b1);
                mma3(a2, ah2, al2, b2);
                mma3(a3, ah3, al3, b3);
            }
            const int ddb = halfA * 8 + 2 * lt;
            gbuf[(lg * 16 + ddb) * 4 + gateA]           = (a0[0] + a1[0]) + (a2[0] + a3[0]);
            gbuf[(lg * 16 + ddb + 1) * 4 + gateA]       = (a0[1] + a1[1]) + (a2[1] + a3[1]);
            gbuf[((lg + 8) * 16 + ddb) * 4 + gateA]     = (a0[2] + a1[2]) + (a2[2] + a3[2]);
            gbuf[((lg + 8) * 16 + ddb + 1) * 4 + gateA] = (a0[3] + a1[3]) + (a2[3] + a3[3]);
        }
        __syncthreads();

        // ---- cell update: write c + s-frags ----
        if (tid < 128) {
            float4 gv0 = *(float4*)&gbuf[(cb * 16 + 2 * cj) * 4];
            float4 gv1 = *(float4*)&gbuf[(cb * 16 + 2 * cj + 1) * 4];
            float si0 = 1.0f / (1.0f + expf(-(gv0.x + xgv[0].x)));
            float sj0 = tanhf(gv0.y + xgv[1].x);
            float sf0 = 1.0f / (1.0f + expf(-(gv0.z + xgv[2].x + 1.0f)));
            float so0 = 1.0f / (1.0f + expf(-(gv0.w + xgv[3].x)));
            float cn0 = sf0 * cold.x + si0 * sj0;
            float s0 = so0 * tanhf(cn0);
            float si1 = 1.0f / (1.0f + expf(-(gv1.x + xgv[0].y)));
            float sj1 = tanhf(gv1.y + xgv[1].y);
            float sf1 = 1.0f / (1.0f + expf(-(gv1.z + xgv[2].y + 1.0f)));
            float so1 = 1.0f / (1.0f + expf(-(gv1.w + xgv[3].y)));
            float cn1 = sf1 * cold.y + si1 * sj1;
            float s1 = so1 * tanhf(cn1);

            *(float2*)&c[cb * DD + d0 + 2 * cj] = make_float2(cn0, cn1);

            unsigned hiw, low;
            bsplit2(s0, s1, hiw, low);
            sfh32[s_idx] = hiw;
            sfl32[s_idx] = low;
        }
        __syncthreads();

        // ---- announce this block's s slice is ready ----
        if (tid == 0) {
            asm volatile("red.release.gpu.global.add.u32 [%0], 1;"
                         :: "l"(&g_sflag[bid * 32]) : "memory");
        }

        // ---- prefetch first proj B-frag pair (static, independent of s) ----
        uint4 pb0 = pp[0];
        uint4 pb1 = pp[32];

        // ---- per-warp wait on the 8 producer blocks of this warp's ksteps ----
        if (lane < 8) {
            unsigned v;
            const unsigned tgt = (unsigned)(t + 1);
            do {
                asm volatile("ld.acquire.gpu.global.u32 %0, [%1];"
                             : "=r"(v) : "l"(myflag) : "memory");
            } while (v < tgt);
        }
        __syncwarp();

        // ---- phase B mma: h = s @ proj ----
        float q0[4] = {0.f, 0.f, 0.f, 0.f};
        float q1[4] = {0.f, 0.f, 0.f, 0.f};
        {
            // peeled first pair (uses prefetched b-frags)
            uint4 ah0 = __ldcg(&aph[0]);
            uint4 al0 = __ldcg(&apl[0]);
            uint4 ah1 = __ldcg(&aph[32]);
            uint4 al1 = __ldcg(&apl[32]);
            mma3(q0, ah0, al0, pb0);
            mma3(q1, ah1, al1, pb1);
#pragma unroll
            for (int ks = 2; ks < 8; ks += 2) {
                uint4 b0 = pp[(size_t)(ks + 0) * 32];
                uint4 b1 = pp[(size_t)(ks + 1) * 32];
                uint4 bh0 = __ldcg(&aph[(ks + 0) * 32]);
                uint4 bl0 = __ldcg(&apl[(ks + 0) * 32]);
                uint4 bh1 = __ldcg(&aph[(ks + 1) * 32]);
                uint4 bl1 = __ldcg(&apl[(ks + 1) * 32]);
                mma3(q0, bh0, bl0, b0);
                mma3(q1, bh1, bl1, b1);
            }
        }
        float accp[4];
#pragma unroll
        for (int r = 0; r < 4; r++) accp[r] = q0[r] + q1[r];

#pragma unroll
        for (int r = 0; r < 4; r++) red[(warp * 32 + lane) * 4 + r] = accp[r];
        __syncthreads();

        if (tid < 128) {
            const int b = hb;
            const int p = hp;
            const int rl = (b & 7) * 4 + (p >> 1);
            const int rr = (b < 8) ? (p & 1) : (2 + (p & 1));
            float v = 0.0f;
#pragma unroll
            for (int w = 0; w < 16; w++) v += red[(w * 32 + rl) * 4 + rr];
            hs[((size_t)(b * T + t)) * PP + p0 + p] = v;
            if (t == T - 1) h[b * PP + p0 + p] = v;
            float vp = __shfl_xor_sync(0xffffffffu, v, 1);
            if ((tid & 1) == 0) {
                unsigned hiw, low;
                bsplit2(v, vp, hiw, low);
                hfh32[h_idx] = hiw;
                hfl32[h_idx] = low;
            }
        }

        // ---- global barrier: all h-frags ready for next step's phase A ----
        grid_barrier((unsigned)(t + 1) * 16, bid);
    }
}

// ================= LayerNorm over rows of 1024 (+ bf16 hi/lo split outputs) =================
__global__ __launch_bounds__(256) void ln_kernel(
    const float* __restrict__ x, const float* __restrict__ gam,
    const float* __restrict__ bet, float* __restrict__ y,
    __nv_bfloat16* __restrict__ yh, __nv_bfloat16* __restrict__ yl)
{
    __shared__ float sred[256];
    const size_t r = blockIdx.x;
    const float* xr = x + r * PP;
    const int tid = threadIdx.x;

    float v[4];
#pragma unroll
    for (int i = 0; i < 4; i++) v[i] = xr[tid + i * 256];
    float sm = v[0] + v[1] + v[2] + v[3];
    sred[tid] = sm;
    __syncthreads();
    for (int off = 128; off > 0; off >>= 1) {
        if (tid < off) sred[tid] += sred[tid + off];
        __syncthreads();
    }
    float mean = sred[0] * (1.0f / 1024.0f);
    __syncthreads();

    float q = 0.0f;
#pragma unroll
    for (int i = 0; i < 4; i++) { float d = v[i] - mean; q += d * d; }
    sred[tid] = q;
    __syncthreads();
    for (int off = 128; off > 0; off >>= 1) {
        if (tid < off) sred[tid] += sred[tid + off];
        __syncthreads();
    }
    float inv = rsqrtf(sred[0] * (1.0f / 1024.0f) + 1e-3f);

#pragma unroll
    for (int i = 0; i < 4; i++) {
        int col = tid + i * 256;
        float o = (v[i] - mean) * inv * gam[col] + bet[col];
        y[r * PP + col] = o;
        __nv_bfloat16 hb = __float2bfloat16(o);
        yh[r * PP + col] = hb;
        yl[r * PP + col] = __float2bfloat16(o - __bfloat162float(hb));
    }
}

// ================= tail =================
__global__ __launch_bounds__(256) void write_tail(
    const float* __restrict__ c, const float* __restrict__ h, float* __restrict__ out)
{
    const size_t base = (size_t)BB * TR * PP;
    int i = blockIdx.x * 256 + threadIdx.x;
    if (i < BB * DD) out[base + i] = c[i];
    if (i < BB * PP) out[base + BB * DD + i] = h[i];
}

// ================= orchestration =================
extern "C" void kernel_launch(void* const* d_in, const int* in_sizes, int n_in,
                              void* d_out, int out_size)
{
    const float* inputs  = (const float*)d_in[0];
    const float* state   = (const float*)d_in[1];
    const float* kernels = (const float*)d_in[2];
    const float* biases  = (const float*)d_in[3];
    const float* projs   = (const float*)d_in[4];
    const float* gamma   = (const float*)d_in[5];
    const float* beta    = (const float*)d_in[6];
    const float* convw   = (const float*)d_in[7];
    const float* convb   = (const float*)d_in[8];
    float* out = (float*)d_out;

    float *xg, *bufA, *hs, *c, *h;
    uint4 *whp, *projp;
    __nv_bfloat16 *wth, *wtl, *axh, *axl, *cah, *cal;
    cudaGetSymbolAddress((void**)&xg,    g_xg);
    cudaGetSymbolAddress((void**)&bufA,  g_bufA);
    cudaGetSymbolAddress((void**)&hs,    g_hs);
    cudaGetSymbolAddress((void**)&whp,   g_whp);
    cudaGetSymbolAddress((void**)&projp, g_projp);
    cudaGetSymbolAddress((void**)&wth,   g_wth);
    cudaGetSymbolAddress((void**)&wtl,   g_wtl);
    cudaGetSymbolAddress((void**)&axh,   g_axh);
    cudaGetSymbolAddress((void**)&axl,   g_axl);
    cudaGetSymbolAddress((void**)&cah,   g_cah);
    cudaGetSymbolAddress((void**)&cal,   g_cal);
    cudaGetSymbolAddress((void**)&c,     g_c);
    cudaGetSymbolAddress((void**)&h,     g_h);

    static int smem_set = 0;
    if (!smem_set) {
        cudaFuncSetAttribute(lstm_persist, cudaFuncAttributeMaxDynamicSharedMemorySize, SMEM_BYTES);
        smem_set = 1;
    }

    setup_all<<<128, 256>>>(state);

    split_x<<<(int)(((size_t)BB * T0 * PP / 4 + 255) / 256), 256>>>(
        inputs, axh, axl, (size_t)BB * T0 * PP / 4);

    int T = T0;
    for (int l = 0; l < NL; l++) {
        const float* Wx = kernels + (size_t)l * 2 * PP * G4;
        const float* Wh = Wx + (size_t)PP * G4;
        const float* bi = biases + (size_t)l * G4;
        const float* pr = projs + (size_t)l * DD * PP;
        const int M = BB * T;

        pack_frag<<<(1024 * 64) / 8, 256>>>(Wh, whp, G4, 64);
        pack_frag<<<(128 * 128) / 8, 256>>>(pr, projp, PP, 128);

        pack_wt<<<dim3(G4 / 32, PP / 32), 256>>>(Wx, wth, wtl, PP, G4);

        dim3 g1(G4 / 128, (M + 127) / 128);
        gemm_sp<<<g1, 256>>>(axh, axl, wth, wtl, bi, xg, M, G4, PP);

        lstm_persist<<<NBLK, 512, SMEM_BYTES>>>(xg, whp, projp, c, h, hs, T);

        float* lnout = (l == 3) ? out : bufA;
        ln_kernel<<<BB * T, 256>>>(hs, gamma, beta, lnout, axh, axl);

        if (l == 1) {
            build_convA_sp<<<(int)(((size_t)BB * TR * DD + 255) / 256), 256>>>(axh, axl, cah, cal);
            pack_wt<<<dim3(PP / 32, DD / 32), 256>>>(convw, wth, wtl, DD, PP);
            dim3 g2(PP / 128, (BB * TR + 127) / 128);
            gemm_sp<<<g2, 256>>>(cah, cal, wth, wtl, convb, bufA, BB * TR, PP, DD);
            split_x<<<(int)(((size_t)BB * TR * PP / 4 + 255) / 256), 256>>>(
                bufA, axh, axl, (size_t)BB * TR * PP / 4);
            T = TR;
        }
    }

    write_tail<<<128, 256>>>(c, h, out);
}